// round 1
// baseline (speedup 1.0000x reference)
#include <cuda_runtime.h>
#include <math.h>

#define BATCH 4096
#define NTAB  26
#define VOC   100000
#define EDIM  64
#define NPAIR 351          // 27*26/2
#define RDIM  415          // 64 + 351

// ---------------- scratch (static device globals; no allocation) ----------------
__device__ float g_h0[BATCH * 512];
__device__ float g_h1[BATCH * 256];
__device__ float g_h [BATCH * 64];
__device__ float g_R [BATCH * RDIM];
__device__ float g_z0[BATCH * 512];
__device__ float g_z1[BATCH * 256];

// ---------------- generic tiled GEMM: C[M,N] = act(A[M,K] @ W[N,K]^T + bias) ----
// ACT: 0 = none, 1 = relu
template <int ACT>
__global__ void __launch_bounds__(256)
gemm_bias_act(const float* __restrict__ A, const float* __restrict__ W,
              const float* __restrict__ bias, float* __restrict__ C,
              int M, int N, int K)
{
    constexpr int BM = 128, BN = 64, BK = 16, TM = 8, TN = 4;
    __shared__ float As[BK][BM + 1];
    __shared__ float Ws[BK][BN + 1];

    const int bm = blockIdx.y * BM;
    const int bn = blockIdx.x * BN;
    const int tid = threadIdx.x;
    const int ty = tid / (BN / TN);   // 0..15 -> rows
    const int tx = tid % (BN / TN);   // 0..15 -> cols

    float acc[TM][TN];
#pragma unroll
    for (int i = 0; i < TM; i++)
#pragma unroll
        for (int j = 0; j < TN; j++) acc[i][j] = 0.f;

    for (int k0 = 0; k0 < K; k0 += BK) {
        // load A tile (BM x BK), transposed into As[k][m]
#pragma unroll
        for (int i = tid; i < BM * BK; i += 256) {
            int r = i / BK, c = i % BK;
            float v = 0.f;
            if (k0 + c < K) v = A[(long long)(bm + r) * K + k0 + c];
            As[c][r] = v;
        }
        // load W tile (BN x BK), transposed into Ws[k][n]
#pragma unroll
        for (int i = tid; i < BN * BK; i += 256) {
            int r = i / BK, c = i % BK;
            float v = 0.f;
            if ((k0 + c < K) && (bn + r < N)) v = W[(long long)(bn + r) * K + k0 + c];
            Ws[c][r] = v;
        }
        __syncthreads();

#pragma unroll
        for (int k = 0; k < BK; k++) {
            float a[TM], w[TN];
#pragma unroll
            for (int i = 0; i < TM; i++) a[i] = As[k][ty * TM + i];
#pragma unroll
            for (int j = 0; j < TN; j++) w[j] = Ws[k][tx * TN + j];
#pragma unroll
            for (int i = 0; i < TM; i++)
#pragma unroll
                for (int j = 0; j < TN; j++) acc[i][j] += a[i] * w[j];
        }
        __syncthreads();
    }

#pragma unroll
    for (int i = 0; i < TM; i++) {
        int m = bm + ty * TM + i;
#pragma unroll
        for (int j = 0; j < TN; j++) {
            int n = bn + tx * TN + j;
            if (n < N) {
                float v = acc[i][j] + bias[n];
                if (ACT == 1) v = fmaxf(v, 0.f);
                C[(long long)m * N + n] = v;
            }
        }
    }
}

// ---------------- fused embedding gather-sum + pairwise interaction ----------------
// One block per batch row. Builds T[27][64] (h + 26 summed embeddings) in shared,
// computes the 351 strict-lower-triangle dot products, writes R[b] = [h | Zflat].
__global__ void __launch_bounds__(128)
interact_kernel(const float* __restrict__ h, const void* __restrict__ lsi,
                const float* __restrict__ emb, float* __restrict__ R)
{
    __shared__ float Ts[27][65];   // pad 65: stride-64 would be a 32-way bank conflict
    __shared__ int s_is64;

    const int b   = blockIdx.x;
    const int tid = threadIdx.x;

    if (tid == 0) {
        // Detect int64 vs int32 indices: valid int64 values are all < VOC; if the
        // buffer is actually int32, u64-reinterpreted words contain the next index
        // in the high 32 bits (>= VOC with prob 1 - 1e-5 each).
        const unsigned long long* q = (const unsigned long long*)lsi;
        int ok = 1;
#pragma unroll
        for (int i = 0; i < 4; i++)
            if (q[i] >= (unsigned long long)VOC) ok = 0;
        s_is64 = ok;
    }
    if (tid < 64) Ts[0][tid] = h[(long long)b * 64 + tid];
    __syncthreads();

    const int warp = tid >> 5, lane = tid & 31;
    const int is64 = s_is64;

    for (int t = warp; t < NTAB; t += 4) {
        float2 s = make_float2(0.f, 0.f);
        const long long base = ((long long)t * BATCH + b) * 4;
#pragma unroll
        for (int l = 0; l < 4; l++) {
            long long pos = base + l;
            int idx = is64 ? (int)((const long long*)lsi)[pos]
                           : ((const int*)lsi)[pos];
            const float2* row =
                (const float2*)(emb + ((long long)t * VOC + idx) * EDIM);
            float2 v = __ldg(&row[lane]);
            s.x += v.x; s.y += v.y;
        }
        Ts[1 + t][2 * lane]     = s.x;
        Ts[1 + t][2 * lane + 1] = s.y;
    }
    __syncthreads();

    // R[b][0:64] = h
    if (tid < 64) R[(long long)b * RDIM + tid] = Ts[0][tid];

    // R[b][64 + p] = T[i] . T[j], lower-tri pairs row-major (tril_indices order)
    for (int p = tid; p < NPAIR; p += 128) {
        int i = (int)((1.0f + sqrtf(1.0f + 8.0f * (float)p)) * 0.5f);
        while (i * (i - 1) / 2 > p) i--;
        while ((i + 1) * i / 2 <= p) i++;
        int j = p - i * (i - 1) / 2;

        float acc = 0.f;
#pragma unroll
        for (int k = 0; k < EDIM; k++) acc += Ts[i][k] * Ts[j][k];
        R[(long long)b * RDIM + 64 + p] = acc;
    }
}

// ---------------- final layer: out[b] = sigmoid(z1[b] . w + b0), K=256 ----------------
__global__ void __launch_bounds__(256)
gemv_sigmoid(const float* __restrict__ A, const float* __restrict__ w,
             const float* __restrict__ bias, float* __restrict__ out)
{
    const int row  = blockIdx.x * 8 + (threadIdx.x >> 5);
    const int lane = threadIdx.x & 31;
    float s = 0.f;
#pragma unroll
    for (int i = 0; i < 8; i++) {
        int k = lane + 32 * i;
        s += A[(long long)row * 256 + k] * w[k];
    }
#pragma unroll
    for (int off = 16; off; off >>= 1) s += __shfl_xor_sync(0xffffffffu, s, off);
    if (lane == 0) out[row] = 1.f / (1.f + expf(-(s + bias[0])));
}

// ---------------- launch ----------------
extern "C" void kernel_launch(void* const* d_in, const int* in_sizes, int n_in,
                              void* d_out, int out_size)
{
    const float* x    = (const float*)d_in[0];
    const void*  lsi  = d_in[1];
    const float* emb  = (const float*)d_in[2];
    const float* bw0  = (const float*)d_in[3];
    const float* bb0  = (const float*)d_in[4];
    const float* bw1  = (const float*)d_in[5];
    const float* bb1  = (const float*)d_in[6];
    const float* bw2  = (const float*)d_in[7];
    const float* bb2  = (const float*)d_in[8];
    const float* tw0  = (const float*)d_in[9];
    const float* tb0  = (const float*)d_in[10];
    const float* tw1  = (const float*)d_in[11];
    const float* tb1  = (const float*)d_in[12];
    const float* tw2  = (const float*)d_in[13];
    const float* tb2  = (const float*)d_in[14];
    float* out = (float*)d_out;

    float *h0, *h1, *h, *R, *z0, *z1;
    cudaGetSymbolAddress((void**)&h0, g_h0);
    cudaGetSymbolAddress((void**)&h1, g_h1);
    cudaGetSymbolAddress((void**)&h,  g_h);
    cudaGetSymbolAddress((void**)&R,  g_R);
    cudaGetSymbolAddress((void**)&z0, g_z0);
    cudaGetSymbolAddress((void**)&z1, g_z1);

    // bottom MLP
    gemm_bias_act<1><<<dim3(512 / 64, BATCH / 128), 256>>>(x,  bw0, bb0, h0, BATCH, 512, 13);
    gemm_bias_act<1><<<dim3(256 / 64, BATCH / 128), 256>>>(h0, bw1, bb1, h1, BATCH, 256, 512);
    gemm_bias_act<1><<<dim3(64  / 64, BATCH / 128), 256>>>(h1, bw2, bb2, h,  BATCH, 64,  256);

    // embeddings + pairwise interaction -> R[B, 415]
    interact_kernel<<<BATCH, 128>>>(h, lsi, emb, R);

    // top MLP
    gemm_bias_act<1><<<dim3(512 / 64, BATCH / 128), 256>>>(R,  tw0, tb0, z0, BATCH, 512, RDIM);
    gemm_bias_act<1><<<dim3(256 / 64, BATCH / 128), 256>>>(z0, tw1, tb1, z1, BATCH, 256, 512);
    gemv_sigmoid<<<BATCH / 8, 256>>>(z1, tw2, tb2, out);
}

// round 2
// speedup vs baseline: 1.7960x; 1.7960x over previous
#include <cuda_runtime.h>
#include <mma.h>
#include <math.h>

using namespace nvcuda;

#define BATCH 4096
#define NTAB  26
#define VOC   100000
#define EDIM  64
#define NPAIR 351          // 27*26/2
#define RDIM  415          // 64 + 351

// ---------------- scratch (static device globals; no allocation) ----------------
__device__ float g_h0[BATCH * 512];
__device__ float g_h1[BATCH * 256];
__device__ float g_h [BATCH * 64];
__device__ float g_R [BATCH * RDIM];
__device__ float g_z0[BATCH * 512];
__device__ float g_z1[BATCH * 256];

// ---------------- tf32 tensor-core GEMM: C[M,N] = relu(A[M,K] @ W[N,K]^T + b) ----
// BM=128, BN=64, BK=32. 8 warps; each warp computes a 32x32 tile via 2x2 wmma
// 16x16x8 tf32 fragments with fp32 accumulation.
template <int ACT>
__global__ void __launch_bounds__(256)
gemm_tf32(const float* __restrict__ A, const float* __restrict__ W,
          const float* __restrict__ bias, float* __restrict__ C,
          int M, int N, int K)
{
    constexpr int BM = 128, BN = 64, BK = 32, LDT = 36, LDC = 36;
    __shared__ float smem[9216];            // max(tiles 6912, Cs 9216)
    float* As = smem;                       // [BM][LDT]
    float* Ws = smem + BM * LDT;            // [BN][LDT]

    const int bm  = blockIdx.y * BM;
    const int bn  = blockIdx.x * BN;
    const int tid = threadIdx.x;
    const int wid = tid >> 5;
    const int lane = tid & 31;
    const int warp_m = wid & 3;             // 0..3
    const int warp_n = wid >> 2;            // 0..1

    wmma::fragment<wmma::accumulator, 16, 16, 8, float> acc[2][2];
#pragma unroll
    for (int i = 0; i < 2; i++)
#pragma unroll
        for (int j = 0; j < 2; j++) wmma::fill_fragment(acc[i][j], 0.f);

    for (int k0 = 0; k0 < K; k0 += BK) {
        // A tile: BM x BK (coalesced, zero-padded beyond K)
#pragma unroll
        for (int i = tid; i < BM * BK; i += 256) {
            int r = i >> 5, c = i & 31;
            float v = 0.f;
            if (k0 + c < K) v = A[(long long)(bm + r) * K + k0 + c];
            As[r * LDT + c] = v;
        }
        // W tile: BN x BK
#pragma unroll
        for (int i = tid; i < BN * BK; i += 256) {
            int r = i >> 5, c = i & 31;
            float v = 0.f;
            if (k0 + c < K) v = W[(long long)(bn + r) * K + k0 + c];
            Ws[r * LDT + c] = v;
        }
        __syncthreads();

#pragma unroll
        for (int kk = 0; kk < BK; kk += 8) {
            wmma::fragment<wmma::matrix_a, 16, 16, 8, wmma::precision::tf32, wmma::row_major> af[2];
            wmma::fragment<wmma::matrix_b, 16, 16, 8, wmma::precision::tf32, wmma::col_major> bf[2];
#pragma unroll
            for (int i = 0; i < 2; i++) {
                wmma::load_matrix_sync(af[i], &As[(warp_m * 32 + i * 16) * LDT + kk], LDT);
#pragma unroll
                for (int e = 0; e < af[i].num_elements; e++)
                    af[i].x[e] = wmma::__float_to_tf32(af[i].x[e]);
            }
#pragma unroll
            for (int j = 0; j < 2; j++) {
                wmma::load_matrix_sync(bf[j], &Ws[(warp_n * 32 + j * 16) * LDT + kk], LDT);
#pragma unroll
                for (int e = 0; e < bf[j].num_elements; e++)
                    bf[j].x[e] = wmma::__float_to_tf32(bf[j].x[e]);
            }
#pragma unroll
            for (int i = 0; i < 2; i++)
#pragma unroll
                for (int j = 0; j < 2; j++)
                    wmma::mma_sync(acc[i][j], af[i], bf[j], acc[i][j]);
        }
        __syncthreads();
    }

    // Epilogue: park accumulators in shared (warp-private region), bias+relu, store
    float* Cs = smem + wid * 32 * LDC;
#pragma unroll
    for (int i = 0; i < 2; i++)
#pragma unroll
        for (int j = 0; j < 2; j++)
            wmma::store_matrix_sync(&Cs[(i * 16) * LDC + j * 16], acc[i][j], LDC, wmma::mem_row_major);

    const int n = bn + warp_n * 32 + lane;
    const float bv = bias[n];
#pragma unroll
    for (int r = 0; r < 32; r++) {
        int m = bm + warp_m * 32 + r;
        float v = Cs[r * LDC + lane] + bv;
        if (ACT == 1) v = fmaxf(v, 0.f);
        C[(long long)m * N + n] = v;
    }
}

// ---------------- fused embedding gather-sum + pairwise interaction ----------------
__global__ void __launch_bounds__(256)
interact_kernel(const float* __restrict__ h, const void* __restrict__ lsi,
                const float* __restrict__ emb, float* __restrict__ R)
{
    __shared__ float Ts[27][68];   // stride 68 floats = 272B: 16B-aligned rows, bank-skewed
    __shared__ int s_is64;

    const int b   = blockIdx.x;
    const int tid = threadIdx.x;

    if (tid == 0) {
        // int64 vs int32 index detection (JAX may silently emit int32)
        const unsigned long long* q = (const unsigned long long*)lsi;
        int ok = 1;
#pragma unroll
        for (int i = 0; i < 4; i++)
            if (q[i] >= (unsigned long long)VOC) ok = 0;
        s_is64 = ok;
    }
    if (tid < 64) Ts[0][tid] = h[(long long)b * 64 + tid];
    __syncthreads();

    const int warp = tid >> 5, lane = tid & 31;
    const int is64 = s_is64;

    for (int t = warp; t < NTAB; t += 8) {
        float2 s = make_float2(0.f, 0.f);
        const long long base = ((long long)t * BATCH + b) * 4;
#pragma unroll
        for (int l = 0; l < 4; l++) {
            long long pos = base + l;
            int idx = is64 ? (int)((const long long*)lsi)[pos]
                           : ((const int*)lsi)[pos];
            const float2* row =
                (const float2*)(emb + ((long long)t * VOC + idx) * EDIM);
            float2 v = __ldg(&row[lane]);
            s.x += v.x; s.y += v.y;
        }
        Ts[1 + t][2 * lane]     = s.x;
        Ts[1 + t][2 * lane + 1] = s.y;
    }
    __syncthreads();

    if (tid < 64) R[(long long)b * RDIM + tid] = Ts[0][tid];

    for (int p = tid; p < NPAIR; p += 256) {
        int i = (int)((1.0f + sqrtf(1.0f + 8.0f * (float)p)) * 0.5f);
        while (i * (i - 1) / 2 > p) i--;
        while ((i + 1) * i / 2 <= p) i++;
        int j = p - i * (i - 1) / 2;

        const float4* ri = (const float4*)&Ts[i][0];
        const float4* rj = (const float4*)&Ts[j][0];
        float acc = 0.f;
#pragma unroll
        for (int k = 0; k < EDIM / 4; k++) {
            float4 a = ri[k], c = rj[k];
            acc += a.x * c.x + a.y * c.y + a.z * c.z + a.w * c.w;
        }
        R[(long long)b * RDIM + 64 + p] = acc;
    }
}

// ---------------- final layer: out[b] = sigmoid(z1[b] . w + b0), K=256 ----------------
__global__ void __launch_bounds__(256)
gemv_sigmoid(const float* __restrict__ A, const float* __restrict__ w,
             const float* __restrict__ bias, float* __restrict__ out)
{
    const int row  = blockIdx.x * 8 + (threadIdx.x >> 5);
    const int lane = threadIdx.x & 31;
    float s = 0.f;
#pragma unroll
    for (int i = 0; i < 8; i++) {
        int k = lane + 32 * i;
        s += A[(long long)row * 256 + k] * w[k];
    }
#pragma unroll
    for (int off = 16; off; off >>= 1) s += __shfl_xor_sync(0xffffffffu, s, off);
    if (lane == 0) out[row] = 1.f / (1.f + expf(-(s + bias[0])));
}

// ---------------- launch ----------------
extern "C" void kernel_launch(void* const* d_in, const int* in_sizes, int n_in,
                              void* d_out, int out_size)
{
    const float* x    = (const float*)d_in[0];
    const void*  lsi  = d_in[1];
    const float* emb  = (const float*)d_in[2];
    const float* bw0  = (const float*)d_in[3];
    const float* bb0  = (const float*)d_in[4];
    const float* bw1  = (const float*)d_in[5];
    const float* bb1  = (const float*)d_in[6];
    const float* bw2  = (const float*)d_in[7];
    const float* bb2  = (const float*)d_in[8];
    const float* tw0  = (const float*)d_in[9];
    const float* tb0  = (const float*)d_in[10];
    const float* tw1  = (const float*)d_in[11];
    const float* tb1  = (const float*)d_in[12];
    const float* tw2  = (const float*)d_in[13];
    const float* tb2  = (const float*)d_in[14];
    float* out = (float*)d_out;

    float *h0, *h1, *h, *R, *z0, *z1;
    cudaGetSymbolAddress((void**)&h0, g_h0);
    cudaGetSymbolAddress((void**)&h1, g_h1);
    cudaGetSymbolAddress((void**)&h,  g_h);
    cudaGetSymbolAddress((void**)&R,  g_R);
    cudaGetSymbolAddress((void**)&z0, g_z0);
    cudaGetSymbolAddress((void**)&z1, g_z1);

    // bottom MLP (tf32 tensor cores)
    gemm_tf32<1><<<dim3(512 / 64, BATCH / 128), 256>>>(x,  bw0, bb0, h0, BATCH, 512, 13);
    gemm_tf32<1><<<dim3(256 / 64, BATCH / 128), 256>>>(h0, bw1, bb1, h1, BATCH, 256, 512);
    gemm_tf32<1><<<dim3(64  / 64, BATCH / 128), 256>>>(h1, bw2, bb2, h,  BATCH, 64,  256);

    // embeddings + pairwise interaction -> R[B, 415]
    interact_kernel<<<BATCH, 256>>>(h, lsi, emb, R);

    // top MLP
    gemm_tf32<1><<<dim3(512 / 64, BATCH / 128), 256>>>(R,  tw0, tb0, z0, BATCH, 512, RDIM);
    gemm_tf32<1><<<dim3(256 / 64, BATCH / 128), 256>>>(z0, tw1, tb1, z1, BATCH, 256, 512);
    gemv_sigmoid<<<BATCH / 8, 256>>>(z1, tw2, tb2, out);
}

// round 3
// speedup vs baseline: 2.6748x; 1.4893x over previous
#include <cuda_runtime.h>
#include <cuda_bf16.h>
#include <mma.h>
#include <math.h>

using namespace nvcuda;

#define BATCH 4096
#define NTAB  26
#define VOC   100000
#define EDIM  64
#define NPAIR 351
#define RDIM  416          // 64 + 351, padded to mult of 16 (col 415 zeroed)

typedef __nv_bfloat16 bf16;

// ---------------- scratch (static device globals; no allocation) ----------------
__device__ bf16  g_xp  [BATCH * 16];
__device__ bf16  g_bw0p[512 * 16];
__device__ bf16  g_bw1p[256 * 512];
__device__ bf16  g_bw2p[64 * 256];
__device__ bf16  g_tw0p[512 * RDIM];
__device__ bf16  g_tw1p[256 * 512];
__device__ bf16  g_h0  [BATCH * 512];
__device__ bf16  g_h1  [BATCH * 256];
__device__ bf16  g_R   [BATCH * RDIM];
__device__ bf16  g_z0  [BATCH * 512];
__device__ bf16  g_z1  [BATCH * 256];
__device__ float g_ly  [BATCH * NTAB * EDIM];   // 27 MB fp32

// ---------------- mega-pack: fp32 -> bf16 with K padded ----------------
struct Seg { const float* src; bf16* dst; int N, K, Kp; };

__global__ void __launch_bounds__(256)
pack_all(const float* x, const float* bw0, const float* bw1, const float* bw2,
         const float* tw0, const float* tw1)
{
    // segment element counts (N*Kp): 65536, 8192, 131072, 16384, 212992, 131072
    long long gid = (long long)blockIdx.x * 256 + threadIdx.x;
    const float* src; bf16* dst; int K, Kp; long long e;
    if (gid < 65536)        { src = x;   dst = g_xp;   K = 13;  Kp = 16;   e = gid; }
    else if (gid < 73728)   { src = bw0; dst = g_bw0p; K = 13;  Kp = 16;   e = gid - 65536; }
    else if (gid < 204800)  { src = bw1; dst = g_bw1p; K = 512; Kp = 512;  e = gid - 73728; }
    else if (gid < 221184)  { src = bw2; dst = g_bw2p; K = 256; Kp = 256;  e = gid - 204800; }
    else if (gid < 434176)  { src = tw0; dst = g_tw0p; K = 415; Kp = RDIM; e = gid - 221184; }
    else if (gid < 565248)  { src = tw1; dst = g_tw1p; K = 512; Kp = 512;  e = gid - 434176; }
    else return;
    int n = (int)(e / Kp), k = (int)(e % Kp);
    float v = (k < K) ? src[(long long)n * K + k] : 0.f;
    dst[e] = __float2bfloat16_rn(v);
}

// ---------------- bf16 tensor-core GEMM: C = relu(A[M,Kp] @ W[N,Kp]^T + b) ----
// BM=128, BN=64, BK=32; 8 warps, each a 32x32 tile (2x2 wmma 16x16x16).
template <int ACT>
__global__ void __launch_bounds__(256)
gemm_bf16(const bf16* __restrict__ A, const bf16* __restrict__ W,
          const float* __restrict__ bias, bf16* __restrict__ C,
          int M, int N, int Kp, int ldc)
{
    constexpr int BM = 128, BN = 64, BK = 32, LDT = 48, LDC = 36;
    __shared__ __align__(16) unsigned char smem_raw[36864];
    bf16* As = (bf16*)smem_raw;                 // [BM][LDT]
    bf16* Ws = As + BM * LDT;                   // [BN][LDT]
    float* Cs = (float*)smem_raw;               // epilogue alias

    const int bm   = blockIdx.y * BM;
    const int bn   = blockIdx.x * BN;
    const int tid  = threadIdx.x;
    const int wid  = tid >> 5;
    const int lane = tid & 31;
    const int warp_m = wid & 3;
    const int warp_n = wid >> 2;

    wmma::fragment<wmma::accumulator, 16, 16, 16, float> acc[2][2];
#pragma unroll
    for (int i = 0; i < 2; i++)
#pragma unroll
        for (int j = 0; j < 2; j++) wmma::fill_fragment(acc[i][j], 0.f);

    const float4 zero4 = make_float4(0.f, 0.f, 0.f, 0.f);

    for (int k0 = 0; k0 < Kp; k0 += BK) {
        // A tile: 128x32 bf16 = 512 float4; 2 per thread
#pragma unroll
        for (int u = 0; u < 2; u++) {
            int i = tid + u * 256;
            int r = i >> 2, c8 = (i & 3) * 8;
            float4 v = zero4;
            if (k0 + c8 < Kp)
                v = *(const float4*)(A + (long long)(bm + r) * Kp + k0 + c8);
            *(float4*)(As + r * LDT + c8) = v;
        }
        // W tile: 64x32 bf16 = 256 float4; 1 per thread
        {
            int r = tid >> 2, c8 = (tid & 3) * 8;
            float4 v = zero4;
            if (k0 + c8 < Kp)
                v = *(const float4*)(W + (long long)(bn + r) * Kp + k0 + c8);
            *(float4*)(Ws + r * LDT + c8) = v;
        }
        __syncthreads();

#pragma unroll
        for (int kk = 0; kk < BK; kk += 16) {
            wmma::fragment<wmma::matrix_a, 16, 16, 16, bf16, wmma::row_major> af[2];
            wmma::fragment<wmma::matrix_b, 16, 16, 16, bf16, wmma::col_major> bf[2];
#pragma unroll
            for (int i = 0; i < 2; i++)
                wmma::load_matrix_sync(af[i], As + (warp_m * 32 + i * 16) * LDT + kk, LDT);
#pragma unroll
            for (int j = 0; j < 2; j++)
                wmma::load_matrix_sync(bf[j], Ws + (warp_n * 32 + j * 16) * LDT + kk, LDT);
#pragma unroll
            for (int i = 0; i < 2; i++)
#pragma unroll
                for (int j = 0; j < 2; j++)
                    wmma::mma_sync(acc[i][j], af[i], bf[j], acc[i][j]);
        }
        __syncthreads();
    }

    // epilogue: park per-warp accumulators in smem, bias+relu, bf16 store
    float* Cw = Cs + wid * 32 * LDC;
#pragma unroll
    for (int i = 0; i < 2; i++)
#pragma unroll
        for (int j = 0; j < 2; j++)
            wmma::store_matrix_sync(Cw + (i * 16) * LDC + j * 16, acc[i][j], LDC, wmma::mem_row_major);
    __syncwarp();

    const int n = bn + warp_n * 32 + lane;
    const float bv = bias[n];
#pragma unroll
    for (int r = 0; r < 32; r++) {
        int m = bm + warp_m * 32 + r;
        float v = Cw[r * LDC + lane] + bv;
        if (ACT == 1) v = fmaxf(v, 0.f);
        C[(long long)m * ldc + n] = __float2bfloat16_rn(v);
    }
}

// ---------------- embedding gather-sum: ly[b][t][:] = sum_l emb[t][idx] ----------
// thread = (b*26 + t, quarter): 4 independent float4 gathers, MLP-saturated.
__global__ void __launch_bounds__(256)
gather_kernel(const void* __restrict__ lsi, const float* __restrict__ emb,
              float* __restrict__ ly)
{
    const long long gid = (long long)blockIdx.x * 256 + threadIdx.x;
    if (gid >= (long long)BATCH * NTAB * 16) return;
    const int pair = (int)(gid >> 4);      // b*26 + t
    const int q4   = (int)(gid & 15);
    const int b = pair / NTAB;
    const int t = pair % NTAB;

    const unsigned long long* q = (const unsigned long long*)lsi;
    const bool is64 = (q[0] < (unsigned long long)VOC) && (q[1] < (unsigned long long)VOC) &&
                      (q[2] < (unsigned long long)VOC) && (q[3] < (unsigned long long)VOC);

    const long long base = ((long long)t * BATCH + b) * 4;
    float4 s = make_float4(0.f, 0.f, 0.f, 0.f);
#pragma unroll
    for (int l = 0; l < 4; l++) {
        int idx = is64 ? (int)((const long long*)lsi)[base + l]
                       : ((const int*)lsi)[base + l];
        float4 v = __ldg((const float4*)(emb + ((long long)t * VOC + idx) * EDIM + q4 * 4));
        s.x += v.x; s.y += v.y; s.z += v.z; s.w += v.w;
    }
    *(float4*)(ly + (long long)pair * EDIM + q4 * 4) = s;
}

// ---------------- interaction: R[b] = [h | tril dots], bf16, stride RDIM --------
__global__ void __launch_bounds__(128)
interact_kernel(const bf16* __restrict__ R_in, const float* __restrict__ ly,
                bf16* __restrict__ R)
{
    __shared__ float Ts[27][68];
    const int b   = blockIdx.x;
    const int tid = threadIdx.x;

    // h from R[:, 0:64] (written by bottom-MLP layer 3)
    if (tid < 64) Ts[0][tid] = __bfloat162float(R_in[(long long)b * RDIM + tid]);
    // ly coalesced: 26*64 floats
    const float* lyb = ly + (long long)b * NTAB * EDIM;
#pragma unroll
    for (int i = tid; i < NTAB * EDIM; i += 128)
        Ts[1 + (i >> 6)][i & 63] = lyb[i];
    __syncthreads();

    for (int p = tid; p < NPAIR; p += 128) {
        int i = (int)((1.0f + sqrtf(1.0f + 8.0f * (float)p)) * 0.5f);
        while (i * (i - 1) / 2 > p) i--;
        while ((i + 1) * i / 2 <= p) i++;
        int j = p - i * (i - 1) / 2;

        const float4* ri = (const float4*)&Ts[i][0];
        const float4* rj = (const float4*)&Ts[j][0];
        float acc = 0.f;
#pragma unroll
        for (int k = 0; k < EDIM / 4; k++) {
            float4 a = ri[k], c = rj[k];
            acc += a.x * c.x + a.y * c.y + a.z * c.z + a.w * c.w;
        }
        R[(long long)b * RDIM + 64 + p] = __float2bfloat16_rn(acc);
    }
    if (tid == 0) R[(long long)b * RDIM + 415] = __float2bfloat16_rn(0.f);
}

// ---------------- final layer: sigmoid(z1 . w + b), K=256, bf16 A ----------------
__global__ void __launch_bounds__(256)
gemv_sigmoid(const bf16* __restrict__ A, const float* __restrict__ w,
             const float* __restrict__ bias, float* __restrict__ out)
{
    const int row  = blockIdx.x * 8 + (threadIdx.x >> 5);
    const int lane = threadIdx.x & 31;
    // 8 consecutive bf16 per lane
    float4 raw = *(const float4*)(A + (long long)row * 256 + lane * 8);
    const __nv_bfloat162* pr = (const __nv_bfloat162*)&raw;
    float s = 0.f;
#pragma unroll
    for (int i = 0; i < 4; i++) {
        float2 v = __bfloat1622float2(pr[i]);
        s += v.x * w[lane * 8 + 2 * i] + v.y * w[lane * 8 + 2 * i + 1];
    }
#pragma unroll
    for (int off = 16; off; off >>= 1) s += __shfl_xor_sync(0xffffffffu, s, off);
    if (lane == 0) out[row] = 1.f / (1.f + expf(-(s + bias[0])));
}

// ---------------- launch ----------------
extern "C" void kernel_launch(void* const* d_in, const int* in_sizes, int n_in,
                              void* d_out, int out_size)
{
    const float* x    = (const float*)d_in[0];
    const void*  lsi  = d_in[1];
    const float* emb  = (const float*)d_in[2];
    const float* bw0  = (const float*)d_in[3];
    const float* bb0  = (const float*)d_in[4];
    const float* bw1  = (const float*)d_in[5];
    const float* bb1  = (const float*)d_in[6];
    const float* bw2  = (const float*)d_in[7];
    const float* bb2  = (const float*)d_in[8];
    const float* tw0  = (const float*)d_in[9];
    const float* tb0  = (const float*)d_in[10];
    const float* tw1  = (const float*)d_in[11];
    const float* tb1  = (const float*)d_in[12];
    const float* tw2  = (const float*)d_in[13];
    const float* tb2  = (const float*)d_in[14];
    float* out = (float*)d_out;

    bf16 *xp, *bw0p, *bw1p, *bw2p, *tw0p, *tw1p, *h0, *h1, *R, *z0, *z1;
    float* ly;
    cudaGetSymbolAddress((void**)&xp,   g_xp);
    cudaGetSymbolAddress((void**)&bw0p, g_bw0p);
    cudaGetSymbolAddress((void**)&bw1p, g_bw1p);
    cudaGetSymbolAddress((void**)&bw2p, g_bw2p);
    cudaGetSymbolAddress((void**)&tw0p, g_tw0p);
    cudaGetSymbolAddress((void**)&tw1p, g_tw1p);
    cudaGetSymbolAddress((void**)&h0,   g_h0);
    cudaGetSymbolAddress((void**)&h1,   g_h1);
    cudaGetSymbolAddress((void**)&R,    g_R);
    cudaGetSymbolAddress((void**)&z0,   g_z0);
    cudaGetSymbolAddress((void**)&z1,   g_z1);
    cudaGetSymbolAddress((void**)&ly,   g_ly);

    // pack weights + x to bf16 (K padded to mult of 16)
    pack_all<<<2208, 256>>>(x, bw0, bw1, bw2, tw0, tw1);

    // embedding gather (independent of MLPs)
    gather_kernel<<<(BATCH * NTAB * 16 + 255) / 256, 256>>>(lsi, emb, ly);

    // bottom MLP (bf16 tensor cores); layer 3 writes into R[:, 0:64]
    gemm_bf16<1><<<dim3(512 / 64, BATCH / 128), 256>>>(xp, bw0p, bb0, h0, BATCH, 512, 16,  512);
    gemm_bf16<1><<<dim3(256 / 64, BATCH / 128), 256>>>(h0, bw1p, bb1, h1, BATCH, 256, 512, 256);
    gemm_bf16<1><<<dim3(64  / 64, BATCH / 128), 256>>>(h1, bw2p, bb2, R,  BATCH, 64,  256, RDIM);

    // pairwise interaction -> R[:, 64:415], zero col 415
    interact_kernel<<<BATCH, 128>>>(R, ly, R);

    // top MLP
    gemm_bf16<1><<<dim3(512 / 64, BATCH / 128), 256>>>(R,  tw0p, tb0, z0, BATCH, 512, RDIM, 512);
    gemm_bf16<1><<<dim3(256 / 64, BATCH / 128), 256>>>(z0, tw1p, tb1, z1, BATCH, 256, 512,  256);
    gemv_sigmoid<<<BATCH / 8, 256>>>(z1, tw2, tb2, out);
}

// round 4
// speedup vs baseline: 3.4275x; 1.2814x over previous
#include <cuda_runtime.h>
#include <cuda_bf16.h>
#include <mma.h>
#include <math.h>

using namespace nvcuda;

#define BATCH 4096
#define NTAB  26
#define VOC   100000
#define EDIM  64
#define NPAIR 351
#define RDIM  416          // 64 + 351 padded (col 415 zeroed)

typedef __nv_bfloat16 bf16;

// ---------------- scratch ----------------
__device__ bf16  g_xp  [BATCH * 32];
__device__ bf16  g_bw0p[512 * 32];
__device__ bf16  g_bw1p[256 * 512];
__device__ bf16  g_bw2p[64 * 256];
__device__ bf16  g_tw0p[512 * RDIM];
__device__ bf16  g_tw1p[256 * 512];
__device__ bf16  g_h0  [BATCH * 512];
__device__ bf16  g_h1  [BATCH * 256];
__device__ bf16  g_R   [BATCH * RDIM];
__device__ bf16  g_z0  [BATCH * 512];
__device__ bf16  g_z1  [BATCH * 256];
__device__ float g_ly  [BATCH * NTAB * EDIM];

// ---------------- helpers ----------------
__device__ __forceinline__ unsigned su(const void* p) {
    return (unsigned)__cvta_generic_to_shared(p);
}
__device__ __forceinline__ void cpa16(unsigned d, const void* s) {
    asm volatile("cp.async.cg.shared.global [%0], [%1], 16;\n" :: "r"(d), "l"(s));
}

// ---------------- mega-pack: fp32 -> bf16, K padded to mult of 32 ----------------
__global__ void __launch_bounds__(256)
pack_all(const float* x, const float* bw0, const float* bw1, const float* bw2,
         const float* tw0, const float* tw1)
{
    long long gid = (long long)blockIdx.x * 256 + threadIdx.x;
    const float* src; bf16* dst; int K, Kp; long long e;
    if (gid < 131072)       { src = x;   dst = g_xp;   K = 13;  Kp = 32;   e = gid; }
    else if (gid < 147456)  { src = bw0; dst = g_bw0p; K = 13;  Kp = 32;   e = gid - 131072; }
    else if (gid < 278528)  { src = bw1; dst = g_bw1p; K = 512; Kp = 512;  e = gid - 147456; }
    else if (gid < 294912)  { src = bw2; dst = g_bw2p; K = 256; Kp = 256;  e = gid - 278528; }
    else if (gid < 507904)  { src = tw0; dst = g_tw0p; K = 415; Kp = RDIM; e = gid - 294912; }
    else if (gid < 638976)  { src = tw1; dst = g_tw1p; K = 512; Kp = 512;  e = gid - 507904; }
    else return;
    int n = (int)(e / Kp), k = (int)(e % Kp);
    float v = (k < K) ? src[(long long)n * K + k] : 0.f;
    dst[e] = __float2bfloat16_rn(v);
}

// ---------------- pipelined bf16 GEMM: C = relu(A[M,Kp] @ W[N,Kp]^T + b) ----
// BM=BN=64, BK=32, 128 threads (4 warps, each a 32x32 tile of 2x2 wmma 16x16x16).
// 2-stage cp.async double buffer; all dims padded -> no predication.
template <int ACT>
__global__ void __launch_bounds__(128, 6)
gemm_bf16(const bf16* __restrict__ A, const bf16* __restrict__ W,
          const float* __restrict__ bias, bf16* __restrict__ C,
          int N, int Kp, int ldc)
{
    constexpr int BM = 64, BN = 64, BK = 32, LDT = 48, LDC = 36;
    __shared__ __align__(16) bf16 sm[2][(BM + BN) * LDT];   // 24.6 KB

    const int bm   = blockIdx.y * BM;
    const int bn   = blockIdx.x * BN;
    const int tid  = threadIdx.x;
    const int wid  = tid >> 5;
    const int lane = tid & 31;
    const int warp_m = wid & 1;
    const int warp_n = wid >> 1;
    const int nk = Kp / BK;

    wmma::fragment<wmma::accumulator, 16, 16, 16, float> acc[2][2];
#pragma unroll
    for (int i = 0; i < 2; i++)
#pragma unroll
        for (int j = 0; j < 2; j++) wmma::fill_fragment(acc[i][j], 0.f);

    const int r0 = tid >> 2, c0 = (tid & 3) * 8;   // 128 thr cover 32 rows x 32 cols /iter... (64 rows via 2 iters)

    // stage loader: A tile 64x32 (256 x 16B chunks), W tile 64x32
    auto load_stage = [&](int st, int k0) {
        bf16* As = sm[st];
        bf16* Ws = As + BM * LDT;
#pragma unroll
        for (int u = 0; u < 2; u++) {
            int r = r0 + u * 32;
            cpa16(su(As + r * LDT + c0), A + (long long)(bm + r) * Kp + k0 + c0);
        }
#pragma unroll
        for (int u = 0; u < 2; u++) {
            int r = r0 + u * 32;
            cpa16(su(Ws + r * LDT + c0), W + (long long)(bn + r) * Kp + k0 + c0);
        }
        asm volatile("cp.async.commit_group;\n");
    };

    load_stage(0, 0);

    for (int it = 0; it < nk; it++) {
        if (it + 1 < nk) {
            load_stage((it + 1) & 1, (it + 1) * BK);
            asm volatile("cp.async.wait_group 1;\n");
        } else {
            asm volatile("cp.async.wait_group 0;\n");
        }
        __syncthreads();

        const bf16* As = sm[it & 1];
        const bf16* Ws = As + BM * LDT;
#pragma unroll
        for (int kk = 0; kk < BK; kk += 16) {
            wmma::fragment<wmma::matrix_a, 16, 16, 16, bf16, wmma::row_major> af[2];
            wmma::fragment<wmma::matrix_b, 16, 16, 16, bf16, wmma::col_major> bfg[2];
#pragma unroll
            for (int i = 0; i < 2; i++)
                wmma::load_matrix_sync(af[i], As + (warp_m * 32 + i * 16) * LDT + kk, LDT);
#pragma unroll
            for (int j = 0; j < 2; j++)
                wmma::load_matrix_sync(bfg[j], Ws + (warp_n * 32 + j * 16) * LDT + kk, LDT);
#pragma unroll
            for (int i = 0; i < 2; i++)
#pragma unroll
                for (int j = 0; j < 2; j++)
                    wmma::mma_sync(acc[i][j], af[i], bfg[j], acc[i][j]);
        }
        __syncthreads();
    }

    // epilogue: park in smem (alias), bias+relu, coalesced bf16 store
    float* Cw = (float*)sm + wid * 32 * LDC;
#pragma unroll
    for (int i = 0; i < 2; i++)
#pragma unroll
        for (int j = 0; j < 2; j++)
            wmma::store_matrix_sync(Cw + (i * 16) * LDC + j * 16, acc[i][j], LDC, wmma::mem_row_major);
    __syncwarp();

    const int n = bn + warp_n * 32 + lane;
    const float bv = bias[n];
#pragma unroll
    for (int r = 0; r < 32; r++) {
        int m = bm + warp_m * 32 + r;
        float v = Cw[r * LDC + lane] + bv;
        if (ACT == 1) v = fmaxf(v, 0.f);
        C[(long long)m * ldc + n] = __float2bfloat16_rn(v);
    }
}

// ---------------- embedding gather-sum ----------------
__global__ void __launch_bounds__(256)
gather_kernel(const void* __restrict__ lsi, const float* __restrict__ emb,
              float* __restrict__ ly)
{
    const long long gid = (long long)blockIdx.x * 256 + threadIdx.x;
    if (gid >= (long long)BATCH * NTAB * 16) return;
    const int pair = (int)(gid >> 4);
    const int q4   = (int)(gid & 15);
    const int b = pair / NTAB;
    const int t = pair % NTAB;

    const unsigned long long* q = (const unsigned long long*)lsi;
    const bool is64 = (q[0] < (unsigned long long)VOC) && (q[1] < (unsigned long long)VOC) &&
                      (q[2] < (unsigned long long)VOC) && (q[3] < (unsigned long long)VOC);

    const long long base = ((long long)t * BATCH + b) * 4;
    float4 s = make_float4(0.f, 0.f, 0.f, 0.f);
#pragma unroll
    for (int l = 0; l < 4; l++) {
        int idx = is64 ? (int)((const long long*)lsi)[base + l]
                       : ((const int*)lsi)[base + l];
        float4 v = __ldg((const float4*)(emb + ((long long)t * VOC + idx) * EDIM + q4 * 4));
        s.x += v.x; s.y += v.y; s.z += v.z; s.w += v.w;
    }
    *(float4*)(ly + (long long)pair * EDIM + q4 * 4) = s;
}

// ---------------- interaction ----------------
__global__ void __launch_bounds__(128)
interact_kernel(const bf16* __restrict__ R_in, const float* __restrict__ ly,
                bf16* __restrict__ R)
{
    __shared__ float Ts[27][68];
    const int b   = blockIdx.x;
    const int tid = threadIdx.x;

    if (tid < 64) Ts[0][tid] = __bfloat162float(R_in[(long long)b * RDIM + tid]);
    const float* lyb = ly + (long long)b * NTAB * EDIM;
#pragma unroll
    for (int i = tid; i < NTAB * EDIM; i += 128)
        Ts[1 + (i >> 6)][i & 63] = lyb[i];
    __syncthreads();

    for (int p = tid; p < NPAIR; p += 128) {
        int i = (int)((1.0f + sqrtf(1.0f + 8.0f * (float)p)) * 0.5f);
        while (i * (i - 1) / 2 > p) i--;
        while ((i + 1) * i / 2 <= p) i++;
        int j = p - i * (i - 1) / 2;

        const float4* ri = (const float4*)&Ts[i][0];
        const float4* rj = (const float4*)&Ts[j][0];
        float acc = 0.f;
#pragma unroll
        for (int k = 0; k < EDIM / 4; k++) {
            float4 a = ri[k], c = rj[k];
            acc += a.x * c.x + a.y * c.y + a.z * c.z + a.w * c.w;
        }
        R[(long long)b * RDIM + 64 + p] = __float2bfloat16_rn(acc);
    }
    if (tid == 0) R[(long long)b * RDIM + 415] = __float2bfloat16_rn(0.f);
}

// ---------------- final layer ----------------
__global__ void __launch_bounds__(256)
gemv_sigmoid(const bf16* __restrict__ A, const float* __restrict__ w,
             const float* __restrict__ bias, float* __restrict__ out)
{
    const int row  = blockIdx.x * 8 + (threadIdx.x >> 5);
    const int lane = threadIdx.x & 31;
    float4 raw = *(const float4*)(A + (long long)row * 256 + lane * 8);
    const __nv_bfloat162* pr = (const __nv_bfloat162*)&raw;
    float s = 0.f;
#pragma unroll
    for (int i = 0; i < 4; i++) {
        float2 v = __bfloat1622float2(pr[i]);
        s += v.x * w[lane * 8 + 2 * i] + v.y * w[lane * 8 + 2 * i + 1];
    }
#pragma unroll
    for (int off = 16; off; off >>= 1) s += __shfl_xor_sync(0xffffffffu, s, off);
    if (lane == 0) out[row] = 1.f / (1.f + expf(-(s + bias[0])));
}

// ---------------- launch ----------------
extern "C" void kernel_launch(void* const* d_in, const int* in_sizes, int n_in,
                              void* d_out, int out_size)
{
    const float* x    = (const float*)d_in[0];
    const void*  lsi  = d_in[1];
    const float* emb  = (const float*)d_in[2];
    const float* bw0  = (const float*)d_in[3];
    const float* bb0  = (const float*)d_in[4];
    const float* bw1  = (const float*)d_in[5];
    const float* bb1  = (const float*)d_in[6];
    const float* bw2  = (const float*)d_in[7];
    const float* bb2  = (const float*)d_in[8];
    const float* tw0  = (const float*)d_in[9];
    const float* tb0  = (const float*)d_in[10];
    const float* tw1  = (const float*)d_in[11];
    const float* tb1  = (const float*)d_in[12];
    const float* tw2  = (const float*)d_in[13];
    const float* tb2  = (const float*)d_in[14];
    float* out = (float*)d_out;

    bf16 *xp, *bw0p, *bw1p, *bw2p, *tw0p, *tw1p, *h0, *h1, *R, *z0, *z1;
    float* ly;
    cudaGetSymbolAddress((void**)&xp,   g_xp);
    cudaGetSymbolAddress((void**)&bw0p, g_bw0p);
    cudaGetSymbolAddress((void**)&bw1p, g_bw1p);
    cudaGetSymbolAddress((void**)&bw2p, g_bw2p);
    cudaGetSymbolAddress((void**)&tw0p, g_tw0p);
    cudaGetSymbolAddress((void**)&tw1p, g_tw1p);
    cudaGetSymbolAddress((void**)&h0,   g_h0);
    cudaGetSymbolAddress((void**)&h1,   g_h1);
    cudaGetSymbolAddress((void**)&R,    g_R);
    cudaGetSymbolAddress((void**)&z0,   g_z0);
    cudaGetSymbolAddress((void**)&z1,   g_z1);
    cudaGetSymbolAddress((void**)&ly,   g_ly);

    pack_all<<<2496, 256>>>(x, bw0, bw1, bw2, tw0, tw1);

    gather_kernel<<<(BATCH * NTAB * 16 + 255) / 256, 256>>>(lsi, emb, ly);

    // bottom MLP; layer 3 writes into R[:, 0:64]
    gemm_bf16<1><<<dim3(8, 64), 128>>>(xp, bw0p, bb0, h0, 512, 32,  512);
    gemm_bf16<1><<<dim3(4, 64), 128>>>(h0, bw1p, bb1, h1, 256, 512, 256);
    gemm_bf16<1><<<dim3(1, 64), 128>>>(h1, bw2p, bb2, R,  64,  256, RDIM);

    interact_kernel<<<BATCH, 128>>>(R, ly, R);

    // top MLP
    gemm_bf16<1><<<dim3(8, 64), 128>>>(R,  tw0p, tb0, z0, 512, RDIM, 512);
    gemm_bf16<1><<<dim3(4, 64), 128>>>(z0, tw1p, tb1, z1, 256, 512,  256);
    gemv_sigmoid<<<BATCH / 8, 256>>>(z1, tw2, tb2, out);
}